// round 8
// baseline (speedup 1.0000x reference)
#include <cuda_runtime.h>
#include <cstddef>

// TokenEmbedding segment-sum, GB300 sm_103a — R7.
// Phase 1: scatter-build boundary table bnd[b][j] = lower_bound(seg_b, j).
// Phase 2: one block per (batch, 4 tokens). Streams the contiguous wordpiece
// range [bnd[j0], bnd[j0+4]) in predicated unroll-4 groups (up to 4 independent
// LDG.128 in flight, no separate tail loop). Row->token routing is computed
// from the boundary values themselves (t = #boundaries <= p), so the inner
// loop has ZERO index loads — only x-row loads. No atomics, no zero-init.

constexpr int B = 16;
constexpr int L = 4096;
constexpr int H = 768;
constexpr int V = H / 4;   // 192 float4 per row
constexpr int T = 4;       // tokens per block

// bnd[b][j] = first wordpiece p with seg[b][p] >= j, for j in [0, L]
__device__ int g_bnd[B][L + 1];

__global__ __launch_bounds__(256) void boundaries_kernel(const int* __restrict__ seg)
{
    const int idx = blockIdx.x * blockDim.x + threadIdx.x;
    if (idx >= B * L) return;
    const int b = idx >> 12;        // / L
    const int p = idx & (L - 1);    // % L
    const int* __restrict__ s = seg + b * L;

    const int sp    = __ldg(s + p);
    const int sprev = (p == 0) ? -1 : __ldg(s + p - 1);

    for (int j = sprev + 1; j <= sp; ++j)
        g_bnd[b][j] = p;

    if (p == L - 1)
        for (int j = sp + 1; j <= L; ++j)
            g_bnd[b][j] = L;
}

__device__ __forceinline__ void accum(float4& a, const float4& v)
{
    a.x += v.x; a.y += v.y; a.z += v.z; a.w += v.w;
}

__device__ __forceinline__ void route(int t, const float4& v,
                                      float4& a0, float4& a1, float4& a2, float4& a3)
{
    if      (t == 0) accum(a0, v);
    else if (t == 1) accum(a1, v);
    else if (t == 2) accum(a2, v);
    else             accum(a3, v);
}

__global__ __launch_bounds__(V) void token_segsum_kernel(
    const float4* __restrict__ x,   // [B, L, V]
    float4*       __restrict__ out) // [B, L, V]
{
    const int b   = blockIdx.y;
    const int j0  = blockIdx.x * T;
    const int col = threadIdx.x;    // 0..191

    const float4* __restrict__ base  = x   + (size_t)b * L * V + col;
    float4*       __restrict__ obase = out + (size_t)b * L * V + (size_t)j0 * V + col;

    const int start = __ldg(&g_bnd[b][j0]);
    const int b1    = __ldg(&g_bnd[b][j0 + 1]);
    const int b2    = __ldg(&g_bnd[b][j0 + 2]);
    const int b3    = __ldg(&g_bnd[b][j0 + 3]);
    const int end   = __ldg(&g_bnd[b][j0 + T]);

    float4 a0 = make_float4(0.f, 0.f, 0.f, 0.f);
    float4 a1 = a0, a2 = a0, a3 = a0;

    #pragma unroll 1
    for (int p = start; p < end; p += 4) {
        // Up to 4 independent predicated loads, front-batched by ptxas.
        float4 v0, v1, v2, v3;
        const bool q0 = true;            // p < end by loop condition
        const bool q1 = (p + 1) < end;
        const bool q2 = (p + 2) < end;
        const bool q3 = (p + 3) < end;
        if (q0) v0 = __ldg(base + (size_t)(p + 0) * V);
        if (q1) v1 = __ldg(base + (size_t)(p + 1) * V);
        if (q2) v2 = __ldg(base + (size_t)(p + 2) * V);
        if (q3) v3 = __ldg(base + (size_t)(p + 3) * V);

        // Routing from boundary registers only — no loads.
        if (q0) route((p + 0 >= b1) + (p + 0 >= b2) + (p + 0 >= b3), v0, a0, a1, a2, a3);
        if (q1) route((p + 1 >= b1) + (p + 1 >= b2) + (p + 1 >= b3), v1, a0, a1, a2, a3);
        if (q2) route((p + 2 >= b1) + (p + 2 >= b2) + (p + 2 >= b3), v2, a0, a1, a2, a3);
        if (q3) route((p + 3 >= b1) + (p + 3 >= b2) + (p + 3 >= b3), v3, a0, a1, a2, a3);
    }

    obase[0 * V] = a0;
    obase[1 * V] = a1;
    obase[2 * V] = a2;
    obase[3 * V] = a3;
}

extern "C" void kernel_launch(void* const* d_in, const int* in_sizes, int n_in,
                              void* d_out, int out_size)
{
    const float4* x   = (const float4*)d_in[0];
    const int*    seg = (const int*)d_in[1];
    float4*       out = (float4*)d_out;

    boundaries_kernel<<<(B * L + 255) / 256, 256>>>(seg);

    dim3 grid(L / T, B);
    token_segsum_kernel<<<grid, V>>>(x, out);
}